// round 15
// baseline (speedup 1.0000x reference)
#include <cuda_runtime.h>
#include <cuda_bf16.h>
#include <math.h>
#include <stdint.h>

// ConvLSTM T=16,B=4,Cin=32,HID=64,H=W=64, 3x3 SAME — HMMA bf16 hi/lo split.
// R15: A operands pre-split in gmem (x once per launch, h in prior step's epilogue);
// A-fill = pure cp.async with zfill halos, double-buffered, overlapped with MMA.

#define T_ 16
#define B_ 4
#define CIN 32
#define HID 64
#define HW 4096

#define A_BYTES 21120                 // 264 rows * 80B
#define OFF_BIAS 0
#define OFF_A 1024
#define OFF_B (OFF_A + 2 * A_BYTES)   // 43264
#define TILE_SM 10240                 // 128 loc-oc rows * 80B
#define GRP_SM (3 * TILE_SM)          // 30720
#define SMEM_TOTAL (OFF_B + 2 * GRP_SM)   // 104704
#define GSTRIDE 132
#define OFF_GATES 1024                // aliases A/B region post-compute

__device__ float g_c[B_ * HID * HW];                         // cell state (4 MB)
__device__ __align__(128) unsigned char g_B[54 * 16384];     // split weights (864 KB)
__device__ __align__(128) unsigned char g_xs[16 * 8 * 262144]; // split x (32 MB)
__device__ __align__(128) unsigned char g_hs[16 * 262144];     // split h_prev (4 MB)

static __device__ __forceinline__ uint32_t s2u(const void* p) {
    uint32_t a;
    asm("{ .reg .u64 t; cvta.to.shared.u64 t, %1; cvt.u32.u64 %0, t; }" : "=r"(a) : "l"(p));
    return a;
}
static __device__ __forceinline__ void ldsm4(unsigned* r, uint32_t addr) {
    asm volatile("ldmatrix.sync.aligned.m8n8.x4.shared.b16 {%0,%1,%2,%3}, [%4];"
                 : "=r"(r[0]), "=r"(r[1]), "=r"(r[2]), "=r"(r[3]) : "r"(addr));
}
static __device__ __forceinline__ void mma16816(float* d, const unsigned* a, const unsigned* b) {
    asm volatile("mma.sync.aligned.m16n8k16.row.col.f32.bf16.bf16.f32 "
                 "{%0,%1,%2,%3}, {%4,%5,%6,%7}, {%8,%9}, {%0,%1,%2,%3};"
                 : "+f"(d[0]), "+f"(d[1]), "+f"(d[2]), "+f"(d[3])
                 : "r"(a[0]), "r"(a[1]), "r"(a[2]), "r"(a[3]), "r"(b[0]), "r"(b[1]));
}
static __device__ __forceinline__ float sigf(float x) {
    return 1.f / (1.f + __expf(-x));
}
static __device__ __forceinline__ uint32_t pkbf(float v0, float v1) {
    __nv_bfloat162 t = __floats2bfloat162_rn(v0, v1);
    return *(uint32_t*)&t;
}

// ---------------- weight prep: split fp32 -> bf16 hi/lo ----------------
__global__ void prep_kernel(const float* __restrict__ w_x2h, const float* __restrict__ w_h2h) {
    const int icg = blockIdx.x / 9, tap = blockIdx.x % 9;
    const int oc = threadIdx.x;
    uint32_t* dst = (uint32_t*)(g_B + (size_t)blockIdx.x * 16384 + oc * 64);
#pragma unroll
    for (int cp = 0; cp < 8; cp++) {
        float w0, w1;
        if (icg < 2) {
            int ic = icg * 16 + 2 * cp;
            w0 = w_x2h[((size_t)oc * CIN + ic) * 9 + tap];
            w1 = w_x2h[((size_t)oc * CIN + ic + 1) * 9 + tap];
        } else {
            int ic = (icg - 2) * 16 + 2 * cp;
            w0 = w_h2h[((size_t)oc * HID + ic) * 9 + tap];
            w1 = w_h2h[((size_t)oc * HID + ic + 1) * 9 + tap];
        }
        __nv_bfloat16 h0 = __float2bfloat16(w0);
        __nv_bfloat16 h1 = __float2bfloat16(w1);
        float l0 = w0 - __bfloat162float(h0);
        float l1 = w1 - __bfloat162float(h1);
        dst[cp]     = ((uint32_t)__bfloat16_as_ushort(h1) << 16) | __bfloat16_as_ushort(h0);
        dst[8 + cp] = pkbf(l0, l1);
    }
}

// ---------------- x prep: split all timesteps once, pixel-major ----------------
// g_xs layout: [t*8 + b*2 + icg][px 0..4095][16B hi(8 u32) | lo(8 u32)] = 64B/px
__global__ void prep_x_kernel(const float* __restrict__ x) {
    const int blk = blockIdx.x;                 // 0..127
    const int t = blk >> 3, b = (blk >> 1) & 3, icg = blk & 1;
    const float* srcb = x + ((size_t)(t * 4 + b) * CIN + icg * 16) * HW;
    uint32_t* dst = (uint32_t*)(g_xs + ((size_t)blk << 18));
    for (int px = threadIdx.x; px < 4096; px += 256) {
        uint32_t w[16];
#pragma unroll
        for (int cp = 0; cp < 8; cp++) {
            float v0 = srcb[(size_t)(2 * cp) * HW + px];
            float v1 = srcb[(size_t)(2 * cp + 1) * HW + px];
            __nv_bfloat16 h0 = __float2bfloat16(v0);
            __nv_bfloat16 h1 = __float2bfloat16(v1);
            float l0 = v0 - __bfloat162float(h0);
            float l1 = v1 - __bfloat162float(h1);
            w[cp]     = ((uint32_t)__bfloat16_as_ushort(h1) << 16) | __bfloat16_as_ushort(h0);
            w[8 + cp] = pkbf(l0, l1);
        }
        uint4* d4 = (uint4*)(dst + px * 16);
        d4[0] = make_uint4(w[0], w[1], w[2], w[3]);
        d4[1] = make_uint4(w[4], w[5], w[6], w[7]);
        d4[2] = make_uint4(w[8], w[9], w[10], w[11]);
        d4[3] = make_uint4(w[12], w[13], w[14], w[15]);
    }
}

// ---------------- per-timestep kernel ----------------
__global__ __launch_bounds__(256, 2)
void step_kernel(int t,
                 const float* __restrict__ b_x2h,
                 const float* __restrict__ b_h2h,
                 float* __restrict__ h_out,         // [B,HID,64,64]
                 int first)
{
    extern __shared__ unsigned char sm[];
    const uint32_t smb = s2u(sm);
    const int tid = threadIdx.x;
    const int wid = tid >> 5, lane = tid & 31;
    const int mi = wid & 3, ni = wid >> 2;     // warp: 32 px x 64 loc-oc (ni 0..1)
    const int y0 = blockIdx.x * 2;
    const int ocg = blockIdx.y;                 // hid half: 0 or 1
    const int b  = blockIdx.z;

    float* sbias = (float*)(sm + OFF_BIAS);
    sbias[tid] = b_x2h[tid] + b_h2h[tid];

    const int idxl = lane & 7, q = lane >> 3;
    uint32_t baseA[2];
#pragma unroll
    for (int mt = 0; mt < 2; mt++) {
        int px = mi * 32 + mt * 16 + ((q & 1) << 3) + idxl;
        int arow = ((px >> 6) + 1) * 66 + (px & 63) + 1;
        baseA[mt] = smb + OFF_A + arow * 80 + ((q >> 1) << 4);
    }
    uint32_t baseB[4];
#pragma unroll
    for (int p = 0; p < 4; p++) {
        int loc = ni * 64 + p * 16 + ((q >> 1) << 3) + idxl;
        baseB[p] = loc * 80 + ((q & 1) << 4);
    }

    float acc[2][8][4];
#pragma unroll
    for (int mt = 0; mt < 2; mt++)
#pragma unroll
        for (int t8 = 0; t8 < 8; t8++)
#pragma unroll
            for (int k = 0; k < 4; k++) acc[mt][t8][k] = 0.f;

    const int NG = first ? 2 : 6;
    const int s_total = NG * 3;

// A-fill: pure cp.async with zfill halos. 264 rows x 4 x 16B.
#define FILL_A(icg_, abuf_) do {                                                     \
    const unsigned char* asrc = ((icg_) < 2)                                         \
        ? g_xs + ((size_t)(t * 8 + b * 2 + (icg_)) << 18)                            \
        : g_hs + ((size_t)(b * 4 + (icg_) - 2) << 18);                               \
    for (int p = tid; p < 1056; p += 256) {                                          \
        int row = p >> 2, j = p & 3;                                                 \
        int rr = row / 66, cc = row - rr * 66;                                       \
        int r_img = y0 - 1 + rr, x_img = cc - 1;                                     \
        bool ok = ((unsigned)r_img < 64u) && ((unsigned)x_img < 64u);                \
        const unsigned char* sp = ok                                                 \
            ? asrc + (((size_t)(r_img * 64 + x_img)) << 6) + j * 16 : asrc;          \
        unsigned sz = ok ? 16u : 0u;                                                 \
        uint32_t dsts = smb + OFF_A + (abuf_) * A_BYTES + row * 80 + j * 16;         \
        asm volatile("cp.async.cg.shared.global [%0], [%1], 16, %2;"                 \
                     :: "r"(dsts), "l"(sp), "r"(sz) : "memory");                     \
    }                                                                                \
} while (0)

#define ISSUE_GRP(s_, buf_) do {                                                     \
    const char* gs0 = (const char*)g_B + ((size_t)(s_)) * (3 * 16384);               \
    _Pragma("unroll")                                                                \
    for (int k2 = 0; k2 < 6; k2++) {                                                 \
        int ii = tid + k2 * 256;                                                     \
        int tj = ii >> 9;                                                            \
        int rr2 = ii & 511;                                                          \
        int loc_ = rr2 >> 2, j_ = rr2 & 3;                                           \
        int ocgl = (loc_ >> 5) * 64 + ocg * 32 + (loc_ & 31);                        \
        uint32_t dsts = smb + OFF_B + (buf_) * GRP_SM + tj * TILE_SM + loc_ * 80 + j_ * 16; \
        asm volatile("cp.async.cg.shared.global [%0], [%1], 16;"                     \
                     :: "r"(dsts), "l"(gs0 + tj * 16384 + ocgl * 64 + j_ * 16) : "memory"); \
    }                                                                                \
} while (0)

    FILL_A(0, 0);
    ISSUE_GRP(0, 0);
    asm volatile("cp.async.commit_group;" ::: "memory");

    for (int s = 0; s < s_total; s++) {
        const int icg = s / 3, grp = s - icg * 3;

        asm volatile("cp.async.wait_group 0;" ::: "memory");
        __syncthreads();      // smem copies visible to all; prior readers done

        // issue next copies (overlap with this step's MMAs)
        {
            bool any = false;
            if (grp == 0 && icg + 1 < NG) { FILL_A(icg + 1, (icg + 1) & 1); any = true; }
            if (s + 1 < s_total)          { ISSUE_GRP(s + 1, (s + 1) & 1); any = true; }
            if (any) asm volatile("cp.async.commit_group;" ::: "memory");
        }

        const uint32_t aoff = (uint32_t)((icg & 1) * A_BYTES);
        const int buf = s & 1;
#pragma unroll
        for (int tt3 = 0; tt3 < 3; tt3++) {
            const int tap = grp * 3 + tt3;
            const int dy = tap / 3 - 1, dx = tap % 3 - 1;
            const int ash = (dy * 66 + dx) * 80;
            unsigned ahi[2][4], alo[2][4];
            ldsm4(ahi[0], baseA[0] + aoff + ash);
            ldsm4(ahi[1], baseA[1] + aoff + ash);
            ldsm4(alo[0], baseA[0] + aoff + ash + 32);
            ldsm4(alo[1], baseA[1] + aoff + ash + 32);

            const uint32_t bb = smb + OFF_B + buf * GRP_SM + tt3 * TILE_SM;
#pragma unroll
            for (int half = 0; half < 2; half++) {
                unsigned bh[2][4], bl[2][4];
                ldsm4(bh[0], bb + baseB[2 * half]);
                ldsm4(bh[1], bb + baseB[2 * half + 1]);
                ldsm4(bl[0], bb + baseB[2 * half] + 32);
                ldsm4(bl[1], bb + baseB[2 * half + 1] + 32);
#pragma unroll
                for (int mt = 0; mt < 2; mt++)
#pragma unroll
                    for (int tt = 0; tt < 4; tt++)
                        mma16816(acc[mt][half * 4 + tt], ahi[mt], &bh[tt >> 1][(tt & 1) * 2]);
#pragma unroll
                for (int mt = 0; mt < 2; mt++)
#pragma unroll
                    for (int tt = 0; tt < 4; tt++)
                        mma16816(acc[mt][half * 4 + tt], alo[mt], &bh[tt >> 1][(tt & 1) * 2]);
#pragma unroll
                for (int mt = 0; mt < 2; mt++)
#pragma unroll
                    for (int tt = 0; tt < 4; tt++)
                        mma16816(acc[mt][half * 4 + tt], ahi[mt], &bl[tt >> 1][(tt & 1) * 2]);
            }
        }
    }

    // ---- store accumulators to gates smem (aliases A/B region) ----
    __syncthreads();
    float* gates = (float*)(sm + OFF_GATES);
    {
        const int tg = lane >> 2, t4 = lane & 3;
#pragma unroll
        for (int mt = 0; mt < 2; mt++) {
#pragma unroll
            for (int t8 = 0; t8 < 8; t8++) {
                int px0 = mi * 32 + mt * 16 + tg;
                int loc0 = ni * 64 + t8 * 8 + t4 * 2;
                gates[px0 * GSTRIDE + loc0]           = acc[mt][t8][0];
                gates[px0 * GSTRIDE + loc0 + 1]       = acc[mt][t8][1];
                gates[(px0 + 8) * GSTRIDE + loc0]     = acc[mt][t8][2];
                gates[(px0 + 8) * GSTRIDE + loc0 + 1] = acc[mt][t8][3];
            }
        }
    }
    __syncthreads();

    // ---- LSTM pointwise + split-h production for next step ----
    unsigned short* hs16 = (unsigned short*)g_hs;
    for (int idx = tid; idx < 128 * 32; idx += 256) {
        const int hl = idx >> 7;            // 0..31
        const int px = idx & 127;
        const int hid = ocg * 32 + hl;
        const int y = y0 + (px >> 6), x = px & 63;
        const float* gp = gates + px * GSTRIDE;
        float ai = gp[hl]      + sbias[hid];
        float af = gp[32 + hl] + sbias[64 + hid];
        float ag = gp[64 + hl] + sbias[128 + hid];
        float ao = gp[96 + hl] + sbias[192 + hid];
        const size_t off = (((size_t)b * HID + hid) * 64 + y) * 64 + x;
        float gi = sigf(ai), gf = sigf(af), gg = tanhf(ag), go = sigf(ao);
        float cprev = first ? 0.f : g_c[off];
        float cn = gf * cprev + gi * gg;
        g_c[off]   = cn;
        float hval = go * tanhf(cn);
        h_out[off] = hval;
        // split write for next step's A
        __nv_bfloat16 hh = __float2bfloat16(hval);
        __nv_bfloat16 hl2 = __float2bfloat16(hval - __bfloat162float(hh));
        const int icg2 = hid >> 4, c = hid & 15;
        const size_t b16 = (((size_t)(b * 4 + icg2) * 4096) + (size_t)(y * 64 + x)) * 32;
        hs16[b16 + c]      = __bfloat16_as_ushort(hh);
        hs16[b16 + 16 + c] = __bfloat16_as_ushort(hl2);
    }
}

extern "C" void kernel_launch(void* const* d_in, const int* in_sizes, int n_in,
                              void* d_out, int out_size)
{
    const float* x     = (const float*)d_in[0];
    const float* w_x2h = (const float*)d_in[1];
    const float* b_x2h = (const float*)d_in[2];
    const float* w_h2h = (const float*)d_in[3];
    const float* b_h2h = (const float*)d_in[4];
    float* out = (float*)d_out;

    cudaFuncSetAttribute(step_kernel,
                         cudaFuncAttributeMaxDynamicSharedMemorySize, SMEM_TOTAL);

    prep_kernel<<<54, 256>>>(w_x2h, w_h2h);
    prep_x_kernel<<<128, 256>>>(x);

    const size_t h_step = (size_t)B_ * HID * HW;
    dim3 grid(32, 2, B_);   // 32 y-tiles, 2 hid-halves, 4 batch
    for (int t = 0; t < T_; t++) {
        step_kernel<<<grid, 256, SMEM_TOTAL>>>(t, b_x2h, b_h2h,
                                               out + (size_t)t * h_step, t == 0 ? 1 : 0);
    }
}

// round 17
// speedup vs baseline: 1.9527x; 1.9527x over previous
#include <cuda_runtime.h>
#include <cuda_fp16.h>
#include <math.h>
#include <stdint.h>

// ConvLSTM T=16,B=4,Cin=32,HID=64,H=W=64, 3x3 SAME — single-term fp16 HMMA.
// gates = conv(x)+conv(h) as implicit GEMM, fp16 operands, fp32 accumulate.
// R17 == R16 resubmit (infra failure): 1-term fp16 (3x fewer MMAs) + CTA phase rotation.

#define T_ 16
#define B_ 4
#define CIN 32
#define HID 64
#define HW 4096

#define A_BYTES 12672                 // 264 rows * 48B
#define OFF_BIAS 0
#define OFF_A 1024
#define OFF_B (OFF_A + 2 * A_BYTES)   // 26368
#define TILE_SM 6144                  // 128 loc-oc rows * 48B
#define GRP_SM (3 * TILE_SM)          // 18432
#define GSTRIDE 132
#define OFF_GATES 1024                // aliases A/B region post-compute
#define SMEM_TOTAL 69632              // max(63232 pipeline, 68608 gates)

__device__ float g_c[B_ * HID * HW];                       // cell state (4 MB)
__device__ __align__(128) unsigned char g_B[54 * 8192];    // fp16 weights (432 KB)

static __device__ __forceinline__ uint32_t s2u(const void* p) {
    uint32_t a;
    asm("{ .reg .u64 t; cvta.to.shared.u64 t, %1; cvt.u32.u64 %0, t; }" : "=r"(a) : "l"(p));
    return a;
}
static __device__ __forceinline__ void ldsm4(unsigned* r, uint32_t addr) {
    asm volatile("ldmatrix.sync.aligned.m8n8.x4.shared.b16 {%0,%1,%2,%3}, [%4];"
                 : "=r"(r[0]), "=r"(r[1]), "=r"(r[2]), "=r"(r[3]) : "r"(addr));
}
static __device__ __forceinline__ void mma16816(float* d, const unsigned* a, const unsigned* b) {
    asm volatile("mma.sync.aligned.m16n8k16.row.col.f32.f16.f16.f32 "
                 "{%0,%1,%2,%3}, {%4,%5,%6,%7}, {%8,%9}, {%0,%1,%2,%3};"
                 : "+f"(d[0]), "+f"(d[1]), "+f"(d[2]), "+f"(d[3])
                 : "r"(a[0]), "r"(a[1]), "r"(a[2]), "r"(a[3]), "r"(b[0]), "r"(b[1]));
}
static __device__ __forceinline__ float sigf(float x) {
    return 1.f / (1.f + __expf(-x));
}
static __device__ __forceinline__ uint32_t pkh(float v0, float v1) {
    __half2 t = __floats2half2_rn(v0, v1);
    return *(uint32_t*)&t;
}

// ---------------- weight prep: fp16 quantize ----------------
// g_B tile (icg*9+tap): 256 oc rows x 32B (16 ch fp16)
__global__ void prep_kernel(const float* __restrict__ w_x2h, const float* __restrict__ w_h2h) {
    const int icg = blockIdx.x / 9, tap = blockIdx.x % 9;
    const int oc = threadIdx.x;
    uint32_t* dst = (uint32_t*)(g_B + (size_t)blockIdx.x * 8192 + oc * 32);
#pragma unroll
    for (int cp = 0; cp < 8; cp++) {
        float w0, w1;
        if (icg < 2) {
            int ic = icg * 16 + 2 * cp;
            w0 = w_x2h[((size_t)oc * CIN + ic) * 9 + tap];
            w1 = w_x2h[((size_t)oc * CIN + ic + 1) * 9 + tap];
        } else {
            int ic = (icg - 2) * 16 + 2 * cp;
            w0 = w_h2h[((size_t)oc * HID + ic) * 9 + tap];
            w1 = w_h2h[((size_t)oc * HID + ic + 1) * 9 + tap];
        }
        dst[cp] = pkh(w0, w1);
    }
}

// ---------------- per-timestep kernel ----------------
__global__ __launch_bounds__(256, 2)
void step_kernel(const float* __restrict__ x_t,     // [B,CIN,64,64]
                 const float* __restrict__ h_prev,  // [B,HID,64,64]
                 const float* __restrict__ b_x2h,
                 const float* __restrict__ b_h2h,
                 float* __restrict__ h_out,         // [B,HID,64,64]
                 int first)
{
    extern __shared__ unsigned char sm[];
    const uint32_t smb = s2u(sm);
    const int tid = threadIdx.x;
    const int wid = tid >> 5, lane = tid & 31;
    const int mi = wid & 3, ni = wid >> 2;     // warp: 32 px x 64 loc-oc (ni 0..1)
    const int y0 = blockIdx.x * 2;
    const int ocg = blockIdx.y;                 // hid half: 0 or 1
    const int b  = blockIdx.z;
    const int bid = blockIdx.x + 32 * (blockIdx.y + 2 * blockIdx.z);
    const int phase = (bid >> 2) & 1;           // co-resident CTAs (+148) differ

    float* sbias = (float*)(sm + OFF_BIAS);
    sbias[tid] = b_x2h[tid] + b_h2h[tid];

    const int idxl = lane & 7, q = lane >> 3;
    uint32_t baseA[2];
#pragma unroll
    for (int mt = 0; mt < 2; mt++) {
        int px = mi * 32 + mt * 16 + ((q & 1) << 3) + idxl;
        int arow = ((px >> 6) + 1) * 66 + (px & 63) + 1;
        baseA[mt] = smb + OFF_A + arow * 48 + ((q >> 1) << 4);
    }
    uint32_t baseB[4];
#pragma unroll
    for (int p = 0; p < 4; p++) {
        int loc = ni * 64 + p * 16 + ((q >> 1) << 3) + idxl;
        baseB[p] = loc * 48 + ((q & 1) << 4);
    }

    float acc[2][8][4];
#pragma unroll
    for (int mt = 0; mt < 2; mt++)
#pragma unroll
        for (int t8 = 0; t8 < 8; t8++)
#pragma unroll
            for (int k = 0; k < 4; k++) acc[mt][t8][k] = 0.f;

    const int NG = first ? 2 : 6;
    const int s_total = NG * 3;
    const int soff = phase * (s_total >> 1);    // rotate group schedule (mult of 3)

// A-fill (fp16): 264 halo rows x 32B, LDG+convert+STS
#define FILL_A(icg_, abuf_) do {                                                     \
    const float* srcb = ((icg_) < 2)                                                 \
        ? x_t    + ((size_t)b * CIN + (icg_) * 16) * HW                              \
        : h_prev + ((size_t)b * HID + ((icg_) - 2) * 16) * HW;                       \
    for (int p = tid; p < 264; p += 256) {                                           \
        int rr = p / 66, cc = p - rr * 66;                                           \
        int r_img = y0 - 1 + rr;                                                     \
        bool ok = (cc >= 1) && (cc <= 64) && ((unsigned)r_img < 64u);                \
        const float* gp = srcb + r_img * 64 + (cc - 1);                              \
        uint32_t* dst = (uint32_t*)(sm + OFF_A + (abuf_) * A_BYTES + p * 48);        \
        _Pragma("unroll")                                                            \
        for (int cp = 0; cp < 8; cp++) {                                             \
            float v0 = ok ? gp[(size_t)(2 * cp) * HW] : 0.f;                         \
            float v1 = ok ? gp[(size_t)(2 * cp + 1) * HW] : 0.f;                     \
            dst[cp] = pkh(v0, v1);                                                   \
        }                                                                            \
    }                                                                                \
} while (0)

// B group: 3 tiles, this CTA's 128 loc-oc rows (fp16, 32B/row)
#define ISSUE_GRP(s_, buf_) do {                                                     \
    const char* gs0 = (const char*)g_B + ((size_t)(s_)) * (3 * 8192);                \
    const int loc_ = tid >> 1, j_ = tid & 1;                                         \
    const int ocgl = (loc_ >> 5) * 64 + ocg * 32 + (loc_ & 31);                      \
    _Pragma("unroll")                                                                \
    for (int tj = 0; tj < 3; tj++) {                                                 \
        uint32_t dsts = smb + OFF_B + (buf_) * GRP_SM + tj * TILE_SM + loc_ * 48 + j_ * 16; \
        asm volatile("cp.async.cg.shared.global [%0], [%1], 16;"                     \
                     :: "r"(dsts), "l"(gs0 + tj * 8192 + ocgl * 32 + j_ * 16) : "memory"); \
    }                                                                                \
    asm volatile("cp.async.commit_group;" ::: "memory");                             \
} while (0)

    ISSUE_GRP((0 + soff) % s_total, 0);

    for (int ss = 0; ss < s_total; ss++) {
        const int s = (ss + soff) % s_total;
        const int icg = s / 3, grp = s - icg * 3;

        if (grp == 0) {
            __syncthreads();              // prior ldsm reads of this A buffer done
            FILL_A(icg, icg & 1);
        }

        asm volatile("cp.async.wait_group 0;" ::: "memory");
        __syncthreads();                  // B group + A visible
        if (ss + 1 < s_total) ISSUE_GRP((ss + 1 + soff) % s_total, (ss + 1) & 1);

        const uint32_t aoff = (uint32_t)((icg & 1) * A_BYTES);
        const int buf = ss & 1;
#pragma unroll
        for (int tt3 = 0; tt3 < 3; tt3++) {
            const int tap = grp * 3 + tt3;
            const int dy = tap / 3 - 1, dx = tap % 3 - 1;
            const int ash = (dy * 66 + dx) * 48;
            unsigned ah[2][4];
            ldsm4(ah[0], baseA[0] + aoff + ash);
            ldsm4(ah[1], baseA[1] + aoff + ash);

            const uint32_t bb = smb + OFF_B + buf * GRP_SM + tt3 * TILE_SM;
#pragma unroll
            for (int half = 0; half < 2; half++) {
                unsigned bh[2][4];
                ldsm4(bh[0], bb + baseB[2 * half]);
                ldsm4(bh[1], bb + baseB[2 * half + 1]);
#pragma unroll
                for (int mt = 0; mt < 2; mt++)
#pragma unroll
                    for (int tt = 0; tt < 4; tt++)
                        mma16816(acc[mt][half * 4 + tt], ah[mt], &bh[tt >> 1][(tt & 1) * 2]);
            }
        }
    }

    // ---- store accumulators to gates smem (aliases A/B region) ----
    __syncthreads();
    float* gates = (float*)(sm + OFF_GATES);
    {
        const int tg = lane >> 2, t4 = lane & 3;
#pragma unroll
        for (int mt = 0; mt < 2; mt++) {
#pragma unroll
            for (int t8 = 0; t8 < 8; t8++) {
                int px0 = mi * 32 + mt * 16 + tg;
                int loc0 = ni * 64 + t8 * 8 + t4 * 2;
                gates[px0 * GSTRIDE + loc0]           = acc[mt][t8][0];
                gates[px0 * GSTRIDE + loc0 + 1]       = acc[mt][t8][1];
                gates[(px0 + 8) * GSTRIDE + loc0]     = acc[mt][t8][2];
                gates[(px0 + 8) * GSTRIDE + loc0 + 1] = acc[mt][t8][3];
            }
        }
    }
    __syncthreads();

    // ---- LSTM pointwise (this CTA's 32 hids) ----
    for (int idx = tid; idx < 128 * 32; idx += 256) {
        const int hl = idx >> 7;            // 0..31
        const int px = idx & 127;
        const int hid = ocg * 32 + hl;
        const int y = y0 + (px >> 6), x = px & 63;
        const float* gp = gates + px * GSTRIDE;
        float ai = gp[hl]      + sbias[hid];
        float af = gp[32 + hl] + sbias[64 + hid];
        float ag = gp[64 + hl] + sbias[128 + hid];
        float ao = gp[96 + hl] + sbias[192 + hid];
        const size_t off = (((size_t)b * HID + hid) * 64 + y) * 64 + x;
        float gi = sigf(ai), gf = sigf(af), gg = tanhf(ag), go = sigf(ao);
        float cprev = first ? 0.f : g_c[off];
        float cn = gf * cprev + gi * gg;
        g_c[off]   = cn;
        h_out[off] = go * tanhf(cn);
    }
}

extern "C" void kernel_launch(void* const* d_in, const int* in_sizes, int n_in,
                              void* d_out, int out_size)
{
    const float* x     = (const float*)d_in[0];
    const float* w_x2h = (const float*)d_in[1];
    const float* b_x2h = (const float*)d_in[2];
    const float* w_h2h = (const float*)d_in[3];
    const float* b_h2h = (const float*)d_in[4];
    float* out = (float*)d_out;

    cudaFuncSetAttribute(step_kernel,
                         cudaFuncAttributeMaxDynamicSharedMemorySize, SMEM_TOTAL);

    prep_kernel<<<54, 256>>>(w_x2h, w_h2h);

    const size_t x_step = (size_t)B_ * CIN * HW;
    const size_t h_step = (size_t)B_ * HID * HW;
    dim3 grid(32, 2, B_);   // 32 y-tiles, 2 hid-halves, 4 batch
    for (int t = 0; t < T_; t++) {
        const float* x_t    = x + (size_t)t * x_step;
        const float* h_prev = (t == 0) ? x : out + (size_t)(t - 1) * h_step;
        float* h_out        = out + (size_t)t * h_step;
        step_kernel<<<grid, 256, SMEM_TOTAL>>>(x_t, h_prev, b_x2h, b_h2h,
                                               h_out, t == 0 ? 1 : 0);
    }
}